// round 1
// baseline (speedup 1.0000x reference)
#include <cuda_runtime.h>
#include <math.h>

// ============================================================================
// The whole 23-op interpolate chain is linear & separable:
//   out[img](47x30) = A(47x64) * X[img](64x64) * B^T(64x30)
// A = product of the 23 per-op H-axis 1D resize matrices,
// B = product of the 23 per-op W-axis 1D resize matrices.
// build_mats_kernel composes them with bit-exact (non-contracted) fp32 index
// math matching the JAX reference; resize_chain_kernel does the two small
// GEMMs per image entirely in shared memory.
// ============================================================================

__device__ __align__(16) float g_At[64 * 48];   // [h][a], a<47 valid, rest 0
__device__ __align__(16) float g_Bt[64 * 32];   // [w][n], n<30 valid, rest 0
__device__ float g_nxt[172 * 64];               // composition scratch

__device__ const int c_out[2][23] = {
    // H-axis output sizes per op
    {16, 32, 20, 80, 16, 32,  16, 32, 20, 80, 16, 32,
     16, 32, 20, 80, 16, 32,  54, 108, 54, 43, 47},
    // W-axis output sizes per op
    {16, 32, 20, 80, 24, 72,  16, 32, 20, 80, 24, 72,
     16, 32, 20, 80, 24, 72,  144, 172, 68, 61, 30}};
__device__ const int c_mode[23] = {0, 0, 0, 0, 0, 0,  1, 1, 1, 1, 1, 1,
                                   2, 2, 2, 2, 2, 2,  0, 1, 1, 2, 2};
__device__ const int c_align[23] = {0, 0, 0, 0, 0, 0,  0, 0, 0, 0, 1, 1,
                                    0, 0, 0, 0, 1, 1,  0, 0, 1, 0, 1};

// PyTorch bicubic (a = -0.75) weights, fp32, no FMA contraction.
__device__ __forceinline__ float cc1f(float t) {
    float u = __fsub_rn(__fmul_rn(1.25f, t), 2.25f);
    u = __fmul_rn(u, t);
    u = __fmul_rn(u, t);
    return __fadd_rn(u, 1.0f);
}
__device__ __forceinline__ float cc2f(float t) {
    float u = __fadd_rn(__fmul_rn(-0.75f, t), 3.75f);
    u = __fsub_rn(__fmul_rn(u, t), 6.0f);
    u = __fmul_rn(u, t);
    return __fadd_rn(u, 3.0f);
}

__global__ void build_mats_kernel() {
    __shared__ float cur[172 * 64];   // current composed matrix, rows x 64
    const int tid = threadIdx.x;
    const int T = blockDim.x;   // 256

    for (int axis = 0; axis < 2; ++axis) {
        // init: identity 64x64
        for (int i = tid; i < 64 * 64; i += T)
            cur[i] = ((i >> 6) == (i & 63)) ? 1.0f : 0.0f;
        __syncthreads();

        int in_n = 64;
        for (int op = 0; op < 23; ++op) {
            const int on = c_out[axis][op];
            const int mode = c_mode[op];
            const int al = c_align[op];

            for (int idx = tid; idx < on * 64; idx += T) {
                const int d = idx >> 6;
                const int j = idx & 63;
                float acc;
                if (mode == 0) {
                    // nearest: idx = min(floor(d * in/out), in-1), fp32 math
                    float ratio = (float)((double)in_n / (double)on);
                    int i0 = (int)floorf(__fmul_rn((float)d, ratio));
                    if (i0 > in_n - 1) i0 = in_n - 1;
                    acc = cur[i0 * 64 + j];
                } else {
                    float src;
                    if (al) {
                        float ratio = (float)((double)(in_n - 1) / (double)(on - 1));
                        src = __fmul_rn((float)d, ratio);
                    } else {
                        float ratio = (float)((double)in_n / (double)on);
                        src = __fsub_rn(__fmul_rn(__fadd_rn((float)d, 0.5f), ratio), 0.5f);
                        if (mode == 1 && src < 0.0f) src = 0.0f;   // bilinear clamp only
                    }
                    float x0 = floorf(src);
                    int i0 = (int)x0;
                    float tt = __fsub_rn(src, x0);
                    if (mode == 1) {
                        int ia = i0 < 0 ? 0 : (i0 > in_n - 1 ? in_n - 1 : i0);
                        int ib = i0 + 1 > in_n - 1 ? in_n - 1 : i0 + 1;
                        acc = (1.0f - tt) * cur[ia * 64 + j] + tt * cur[ib * 64 + j];
                    } else {
                        float w0 = cc2f(__fadd_rn(tt, 1.0f));
                        float w1 = cc1f(tt);
                        float w2 = cc1f(__fsub_rn(1.0f, tt));
                        float w3 = cc2f(__fsub_rn(2.0f, tt));
                        int k0 = i0 - 1, k1 = i0, k2 = i0 + 1, k3 = i0 + 2;
                        k0 = k0 < 0 ? 0 : (k0 > in_n - 1 ? in_n - 1 : k0);
                        k1 = k1 < 0 ? 0 : (k1 > in_n - 1 ? in_n - 1 : k1);
                        k2 = k2 < 0 ? 0 : (k2 > in_n - 1 ? in_n - 1 : k2);
                        k3 = k3 < 0 ? 0 : (k3 > in_n - 1 ? in_n - 1 : k3);
                        acc = w0 * cur[k0 * 64 + j] + w1 * cur[k1 * 64 + j] +
                              w2 * cur[k2 * 64 + j] + w3 * cur[k3 * 64 + j];
                    }
                }
                g_nxt[idx] = acc;
            }
            __syncthreads();
            for (int idx = tid; idx < on * 64; idx += T) cur[idx] = g_nxt[idx];
            __syncthreads();
            in_n = on;
        }

        // cur is (final_rows x 64). Store transposed + padded for the GEMM kernel.
        if (axis == 0) {
            for (int idx = tid; idx < 64 * 48; idx += T) {
                int h = idx / 48, a = idx % 48;
                g_At[idx] = (a < 47) ? cur[a * 64 + h] : 0.0f;
            }
        } else {
            for (int idx = tid; idx < 64 * 32; idx += T) {
                int k = idx >> 5, n = idx & 31;
                g_Bt[idx] = (n < 30) ? cur[n * 64 + k] : 0.0f;
            }
        }
        __syncthreads();
    }
}

// ============================================================================
// Main kernel: one CTA per (n,c) image. out = A * (X * B^T).
// ============================================================================
__global__ void __launch_bounds__(128) resize_chain_kernel(
    const float* __restrict__ x, float* __restrict__ out) {
    __shared__ __align__(16) float sX[64][65];    // X[h][w], pad 65 (scalar reads)
    __shared__ __align__(16) float sBt[64][36];   // B^T[w][n] (float4 reads)
    __shared__ __align__(16) float sAt[64][48];   // A^T[h][a] (float4 reads)
    __shared__ __align__(16) float sT[64][36];    // T[h][n] = (X*B^T)[h][n]

    const int t = threadIdx.x;
    const float* __restrict__ xi = x + (size_t)blockIdx.x * 4096;

    // load X (64x64 = 1024 float4)
    #pragma unroll
    for (int v = t; v < 1024; v += 128) {
        float4 q = __ldg((const float4*)xi + v);
        int h = v >> 4, w = (v & 15) << 2;
        sX[h][w] = q.x; sX[h][w + 1] = q.y; sX[h][w + 2] = q.z; sX[h][w + 3] = q.w;
    }
    // load B^T (64x32 = 512 float4)
    #pragma unroll
    for (int v = t; v < 512; v += 128) {
        float4 q = *((const float4*)g_Bt + v);
        *(float4*)&sBt[v >> 3][(v & 7) << 2] = q;
    }
    // load A^T (64x48 = 768 float4)
    #pragma unroll
    for (int v = t; v < 768; v += 128) {
        float4 q = *((const float4*)g_At + v);
        *(float4*)&sAt[v / 12][(v % 12) << 2] = q;
    }
    __syncthreads();

    // ---- phase 1: T(64x32) = X(64x64) * B^T(64x32), 4x4 register tile ----
    {
        const int n0 = (t & 7) << 2;    // 8 n-tiles
        const int h0 = (t >> 3) << 2;   // 16 h-tiles
        float acc[4][4] = {};
        #pragma unroll 4
        for (int k = 0; k < 64; ++k) {
            const float4 b = *(const float4*)&sBt[k][n0];
            #pragma unroll
            for (int i = 0; i < 4; ++i) {
                const float xv = sX[h0 + i][k];
                acc[i][0] = fmaf(xv, b.x, acc[i][0]);
                acc[i][1] = fmaf(xv, b.y, acc[i][1]);
                acc[i][2] = fmaf(xv, b.z, acc[i][2]);
                acc[i][3] = fmaf(xv, b.w, acc[i][3]);
            }
        }
        #pragma unroll
        for (int i = 0; i < 4; ++i)
            *(float4*)&sT[h0 + i][n0] =
                make_float4(acc[i][0], acc[i][1], acc[i][2], acc[i][3]);
    }
    __syncthreads();

    // ---- phase 2: out(47x30) = A(47x64) * T(64x30), 4x4 register tile ----
    if (t < 96) {
        const int n0 = (t & 7) << 2;    // 8 n-tiles
        const int a0 = (t >> 3) << 2;   // 12 a-tiles (48 rows, row 47 padded)
        float acc[4][4] = {};
        #pragma unroll 4
        for (int h = 0; h < 64; ++h) {
            const float4 av = *(const float4*)&sAt[h][a0];
            const float4 tv = *(const float4*)&sT[h][n0];
            acc[0][0] = fmaf(av.x, tv.x, acc[0][0]);
            acc[0][1] = fmaf(av.x, tv.y, acc[0][1]);
            acc[0][2] = fmaf(av.x, tv.z, acc[0][2]);
            acc[0][3] = fmaf(av.x, tv.w, acc[0][3]);
            acc[1][0] = fmaf(av.y, tv.x, acc[1][0]);
            acc[1][1] = fmaf(av.y, tv.y, acc[1][1]);
            acc[1][2] = fmaf(av.y, tv.z, acc[1][2]);
            acc[1][3] = fmaf(av.y, tv.w, acc[1][3]);
            acc[2][0] = fmaf(av.z, tv.x, acc[2][0]);
            acc[2][1] = fmaf(av.z, tv.y, acc[2][1]);
            acc[2][2] = fmaf(av.z, tv.z, acc[2][2]);
            acc[2][3] = fmaf(av.z, tv.w, acc[2][3]);
            acc[3][0] = fmaf(av.w, tv.x, acc[3][0]);
            acc[3][1] = fmaf(av.w, tv.y, acc[3][1]);
            acc[3][2] = fmaf(av.w, tv.z, acc[3][2]);
            acc[3][3] = fmaf(av.w, tv.w, acc[3][3]);
        }
        float* op = out + (size_t)blockIdx.x * 1410;   // 47*30
        #pragma unroll
        for (int i = 0; i < 4; ++i) {
            const int a = a0 + i;
            if (a < 47) {
                #pragma unroll
                for (int j = 0; j < 4; ++j) {
                    const int n = n0 + j;
                    if (n < 30) op[a * 30 + n] = acc[i][j];
                }
            }
        }
    }
}

extern "C" void kernel_launch(void* const* d_in, const int* in_sizes, int n_in,
                              void* d_out, int out_size) {
    const float* x = (const float*)d_in[0];
    float* out = (float*)d_out;
    const int imgs = in_sizes[0] / 4096;   // 32*256 = 8192 images of 64x64

    build_mats_kernel<<<1, 256>>>();
    resize_chain_kernel<<<imgs, 128>>>(x, out);
}